// round 12
// baseline (speedup 1.0000x reference)
#include <cuda_runtime.h>

#define TT 300
#define NB 4

// ---------------- static device buffers (masks padded +8 planes for prefetch) ----------------
__device__ unsigned long long g_r0[TT*NB*2*34];                      // input row masks, bit (x+2)
__device__ __align__(16) unsigned int g_M1[(TT+8)*NB*1156];          // spikes L1: 24ch bits / pixel
__device__ unsigned int g_M2[TT*NB*289];                             // spikes P1
__device__ __align__(16) unsigned int g_M3[(TT+8)*NB*289*2];         // spikes L2: 48ch in 2 words
__device__ unsigned int g_M4[TT*NB*81*2];                            // spikes P2
__device__ __align__(16) unsigned int g_M5[(TT+8)*NB*81*3];          // spikes L3: 96ch in 3 words
__device__ unsigned int g_M6[TT*NB*25*3];                            // spikes P3
__device__ unsigned int g_M7[TT*NB*8];                               // spikes dense1: 256 bits

__device__ float g_A1[(size_t)TT*NB*1156*32];                        // conv1 pre-act (pad 24->32)
__device__ float g_A2[(size_t)TT*NB*289*64];                         // conv2 pre-act (pad 48->64)
__device__ float g_A3[(size_t)TT*NB*81*96];                          // conv3 pre-act
__device__ __align__(16) float g_A7[TT*NB*256];                      // dense1 pre-act
__device__ float g_A8T[NB*16*TT];                                    // dense2 pre-act, [b][o][t]

// zero-padded conv weight tables (out-of-range taps read 0.0 -> no predicates)
__device__ float  g_Wt1x[5*2*11*32];    // [ky][c][u=kx+3: 0..10][o pad32]
__device__ float2 g_Wt2x[48*3*5*32];    // [c][ky][u=xi+1: 0..4][lane] -> (o, o+32)
__device__ float4 g_Wt3x[48*3*5*32];    // [c][ky][u=xi+1: 0..4][lane] -> (o, +32, +64, pad)
__device__ __align__(16) float g_Wt4[2400*256];  // [(c*25+pos)][o 256]
__device__ float  g_Wt5[256*16];        // [i][o pad16]

// ---------------- SRM step: psp (tau=10) + spike w/ refractory (tau=1) ----------------
__device__ __forceinline__ float srm_step(float& p1, float& q1, float& p2, float& q2, float x) {
    const float A1 = 0.90483741803595952f;   // exp(-1/10)
    const float C1 = 0.27182818284590452f;   // e/10
    const float A2 = 0.36787944117144233f;   // exp(-1)
    const float C2 = 2.71828182845904523f;   // e
    const float RR = 20.0f * C2;             // SCALE_REF*THETA*c
    q1 = A1*q1 + A1*p1;
    p1 = A1*p1 + x;
    float y = C1 * q1;
    q2 = A2*q2 + A2*p2;
    float u = y - RR*q2;
    float s = (u >= 10.0f) ? 1.0f : 0.0f;
    p2 = A2*p2 + s;
    return s;
}

// ---------------- SRM scan: warp = 32 neurons, PF=12 rolling ring, 512-thr blocks ----------------
__device__ __forceinline__ void srm_scan_body(const float* __restrict__ in,
                                              unsigned int* __restrict__ out, int nW) {
    int w = blockIdx.x * 16 + (threadIdx.x >> 5);
    int lane = threadIdx.x & 31;
    if (w >= nW) return;
    size_t S = (size_t)nW * 32;
    const float* ip = in + (size_t)w*32 + lane;
    const int PF = 12;
    float buf[PF];
#pragma unroll
    for (int k = 0; k < PF; k++) buf[k] = ip[(size_t)k*S];
    const float* pf = ip + (size_t)PF*S;
    unsigned int* op = out + w;
    float p1=0,q1=0,p2=0,q2=0;
#pragma unroll 1
    for (int t0 = 0; t0 < TT - PF; t0 += PF) {          // 288 main steps
#pragma unroll
        for (int k = 0; k < PF; k++) {
            float x = buf[k];
            buf[k] = *pf; pf += S;                       // prefetch t+PF (max 299)
            float s = srm_step(p1, q1, p2, q2, x);
            unsigned bal = __ballot_sync(0xffffffffu, s > 0.5f);
            if (!lane) *op = bal;
            op += nW;
        }
    }
#pragma unroll
    for (int k = 0; k < PF; k++) {                       // t = 288..299
        float s = srm_step(p1, q1, p2, q2, buf[k]);
        unsigned bal = __ballot_sync(0xffffffffu, s > 0.5f);
        if (!lane) *op = bal;
        op += nW;
    }
}

__global__ void __launch_bounds__(512) srm_scan_L1() { srm_scan_body(g_A1, g_M1, NB*1156);  }
__global__ void __launch_bounds__(512) srm_scan_L2() { srm_scan_body(g_A2, g_M3, NB*289*2); }
__global__ void __launch_bounds__(512) srm_scan_L3() { srm_scan_body(g_A3, g_M5, NB*81*3);  }
__global__ void __launch_bounds__(512) srm_scan_D1() { srm_scan_body(g_A7, g_M7, NB*8);     }

// ---------------- init: zero-padded weight tables ----------------
__global__ void init_weights(const float* __restrict__ Wc1, const float* __restrict__ Wc2,
                             const float* __restrict__ Wc3, const float* __restrict__ Wd4b) {
    int i = blockIdx.x * 256 + threadIdx.x;
    if (i < 5*2*11*32) {                                 // conv1 padded table
        int q = i >> 5, o = i & 31;
        int ky = q / 22, rem = q % 22, c = rem / 11, u = rem % 11;
        int kx = u - 3;
        g_Wt1x[i] = (o < 24 && kx >= 0 && kx < 5) ? Wc1[o*50 + c*25 + ky*5 + kx] : 0.f;
    }
    if (i < 48*3*5*32) {                                 // conv2 + conv3 slot tables
        int q = i >> 5, l = i & 31;
        int c = q / 15, rem = q % 15, ky = rem / 5, u = rem % 5;
        int kx = u - 1;
        float2 v2 = make_float2(0.f, 0.f);
        float4 v3 = make_float4(0.f, 0.f, 0.f, 0.f);
        if (kx >= 0 && kx < 3) {
            int tap = c*9 + ky*3 + kx;
            v2.x = Wc2[l*216 + tap];
            v2.y = (l < 16) ? Wc2[(l + 32)*216 + tap] : 0.f;
            v3 = make_float4(Wc3[l*432 + tap], Wc3[(l + 32)*432 + tap],
                             Wc3[(l + 64)*432 + tap], 0.f);
        }
        g_Wt2x[i] = v2;
        g_Wt3x[i] = v3;
    }
    if (i < 256*16) {
        int r = i >> 4, o = i & 15;
        g_Wt5[i] = (o < 10) ? Wd4b[o*256 + r] : 0.f;
    }
}

// ---------------- pack s_in -> row bitmasks; warp=(b,c,y,t-chunk), lane=t: coalesced ----------------
__global__ void __launch_bounds__(512) pack_input(const float* __restrict__ s_in) {
    int w = blockIdx.x * 16 + (threadIdx.x >> 5);
    int lane = threadIdx.x & 31;
    if (w >= NB*2*34*10) return;
    int chunk = w % 10;
    int r = w / 10;
    int y = r % 34; r /= 34;
    int c = r % 2;
    int b = r / 2;
    int t = chunk * 32 + lane;
    bool tv = t < TT;
    const float* sp = s_in + ((size_t)((b*2 + c)*34 + y)*34)*TT + (tv ? t : 0);
    unsigned long long m = 0ull;
#pragma unroll
    for (int x = 0; x < 34; x++) {
        float v = sp[(size_t)x*TT];                      // lane-coalesced along t
        m |= (unsigned long long)(v != 0.f) << (x + 2);
    }
    if (tv) g_r0[((size_t)(t*NB + b)*2 + c)*34 + y] = m;
}

// ---------------- coalesced smem-tiled transpose of Wd4a -> g_Wt4 ----------------
__global__ void prep_wt4(const float* __restrict__ Wd4a) {
    __shared__ float tile[32][33];
    int r0 = blockIdx.x * 32, o0 = blockIdx.y * 32;
    int tx = threadIdx.x, ty = threadIdx.y;              // 32 x 8
#pragma unroll
    for (int j = 0; j < 32; j += 8)
        tile[ty + j][tx] = Wd4a[(size_t)(o0 + ty + j)*2400 + r0 + tx];   // coalesced in r
    __syncthreads();
#pragma unroll
    for (int j = 0; j < 32; j += 8)
        g_Wt4[(size_t)(r0 + ty + j)*256 + o0 + tx] = tile[tx][ty + j];   // coalesced in o
}

// ---------------- conv1 acc: warp per (t,b,x-QUAD), event-direct, padded weights ----------------
__global__ void __launch_bounds__(256) conv1_acc() {
    int gw = blockIdx.x * 8 + (threadIdx.x >> 5);
    int lane = threadIdx.x & 31;
    if (gw >= TT*NB*306) return;                         // 34 rows x 9 quads
    int pr = gw % 306, tb = gw / 306;
    int y = pr / 9, x0 = (pr % 9) * 4;
    const unsigned long long* rt = g_r0 + (size_t)tb*68;
    const float* wl = g_Wt1x + lane;
    float a0 = 0.f, a1 = 0.f, a2 = 0.f, a3 = 0.f;
#pragma unroll
    for (int ky = 0; ky < 5; ky++) {
        int yy = y + ky - 2;
        if (yy < 0 || yy >= 34) continue;
        unsigned w0 = (unsigned)(rt[yy] >> x0) & 0xFFu;        // taps for pixels x0..x0+3, c=0
        unsigned w1 = (unsigned)(rt[34 + yy] >> x0) & 0xFFu;   // c=1
        unsigned f = w0 | (w1 << 8);
        if (!f) continue;                                // early-out: common at 3% density
        const float* wk = wl + ky*704;                   // ky*2*11*32
        do {
            int bit = __ffs(f) - 1; f &= f - 1;
            int c = bit >> 3, j = bit & 7;               // j = input col - x0
            const float* wr = wk + c*352 + (j << 5);     // slot u=j (kx = j - p -> u = j-p+3)
            a3 += wr[0];                                 // p=3: u=j   (+0)
            a2 += wr[32];                                // p=2: u=j+1
            a1 += wr[64];                                // p=1: u=j+2
            a0 += wr[96];                                // p=0: u=j+3
        } while (f);
    }
    size_t base = ((size_t)tb*1156 + y*34 + x0)*32;
    g_A1[base + lane]      = a0;
    g_A1[base + 32 + lane] = a1;
    if (x0 + 2 < 34) {                                   // last quad has only 2 valid pixels
        g_A1[base + 64 + lane] = a2;
        g_A1[base + 96 + lane] = a3;
    }
}

// ---------------- pool1 + SRM fused: warp per (b,opix), uint2 loads, PF=8, rolling ptrs ----------------
__global__ void __launch_bounds__(512) pool1_srm() {
    int w = blockIdx.x * 16 + (threadIdx.x >> 5);
    int lane = threadIdx.x & 31;
    if (w >= NB*289) return;
    int b = w / 289, pix = w % 289;
    int y = pix / 17, x = pix % 17;
    int p0 = b*1156 + 2*y*34 + 2*x;                      // even -> uint2 aligned
    const int ST = 2312;                                 // uint2 per t-plane
    const uint2* mA = (const uint2*)g_M1 + (p0 >> 1);
    const uint2* mB = mA + 17;
    uint2 bufA[8], bufB[8];
#pragma unroll
    for (int k = 0; k < 8; k++) { bufA[k] = mA[k*ST]; bufB[k] = mB[k*ST]; }
    const uint2* pA = mA + 8*ST;
    const uint2* pB = mB + 8*ST;
    unsigned int* op = g_M2 + w;
    float p1 = 0, q1 = 0, p2 = 0, q2 = 0;
#pragma unroll 1
    for (int t0 = 0; t0 < 296; t0 += 8) {
#pragma unroll
        for (int k = 0; k < 8; k++) {
            uint2 a = bufA[k], c = bufB[k];
            bufA[k] = *pA; pA += ST;                     // padded planes
            bufB[k] = *pB; pB += ST;
            int cnt = ((a.x >> lane) & 1) + ((a.y >> lane) & 1)
                    + ((c.x >> lane) & 1) + ((c.y >> lane) & 1);
            float s = srm_step(p1, q1, p2, q2, 11.0f * (float)cnt);
            unsigned bal = __ballot_sync(0xffffffffu, s > 0.5f);
            if (!lane) *op = bal;
            op += NB*289;
        }
    }
#pragma unroll
    for (int k = 0; k < 4; k++) {                        // t = 296..299
        int cnt = ((bufA[k].x >> lane) & 1) + ((bufA[k].y >> lane) & 1)
                + ((bufB[k].x >> lane) & 1) + ((bufB[k].y >> lane) & 1);
        float s = srm_step(p1, q1, p2, q2, 11.0f * (float)cnt);
        unsigned bal = __ballot_sync(0xffffffffu, s > 0.5f);
        if (!lane) *op = bal;
        op += NB*289;
    }
}

// ---------------- conv2 acc: warp per (t,b,x-PAIR), padded slot weights ----------------
__global__ void __launch_bounds__(256) conv2_acc() {
    int gw = blockIdx.x * 8 + (threadIdx.x >> 5);
    int lane = threadIdx.x & 31;
    if (gw >= TT*NB*153) return;                         // 17 rows x 9 pairs
    int pr = gw % 153, tb = gw / 153;
    int y = pr / 9, x0 = (pr % 9) * 2;
    bool x1v = (x0 + 1) < 17;
    const unsigned* mm = g_M2 + (size_t)tb*289;
    const float2* wl = g_Wt2x + lane;
    float aa0 = 0.f, ab0 = 0.f, aa1 = 0.f, ab1 = 0.f;
#pragma unroll
    for (int ky = 0; ky < 3; ky++) {
        int yy = y + ky - 1;
        if (yy < 0 || yy >= 17) continue;
        const unsigned* row = mm + yy*17;
#pragma unroll
        for (int xi = 0; xi < 4; xi++) {                 // input cols x0-1 .. x0+2
            int xx = x0 - 1 + xi;
            unsigned m = 0u;
            if (xx >= 0 && xx < 17 && (xi < 3 || x1v)) m = row[xx];
            while (m) {
                int c = __ffs(m) - 1; m &= m - 1;
                const float2* wb = wl + c*480 + (ky*5 + xi)*32;   // slot u=xi
                float2 w1v = wb[0];                               // pixel1: kt=ky*3+xi-1
                float2 w0v = wb[32];                              // pixel0: kt=ky*3+xi
                aa0 += w0v.x; ab0 += w0v.y;
                aa1 += w1v.x; ab1 += w1v.y;
            }
        }
    }
    size_t base = ((size_t)tb*289 + y*17 + x0)*64;
    g_A2[base + lane]      = aa0;
    g_A2[base + 32 + lane] = ab0;
    if (x1v) {
        g_A2[base + 64 + lane] = aa1;
        g_A2[base + 96 + lane] = ab1;
    }
}

// ---------------- pool2 + SRM fused: warp per (b,opix,half), PF=8, rolling ptrs ----------------
__global__ void __launch_bounds__(512) pool2_srm() {
    int w = blockIdx.x * 16 + (threadIdx.x >> 5);
    int lane = threadIdx.x & 31;
    if (w >= NB*162) return;
    int b = w / 162, r = w % 162, pix = r >> 1, half = r & 1;
    int y = pix / 9, x = pix % 9;
    bool xv = (2*x + 1) < 17, yv = (2*y + 1) < 17;
    const int ST = 2312;                                 // words per t-plane
    const unsigned* m0 = g_M3 + b*578 + (2*y*17 + 2*x)*2 + half;
    const unsigned* m1 = m0 + 2;
    const unsigned* m2 = m0 + 34;
    const unsigned* m3 = m0 + 36;
    unsigned buf[8][4];
#pragma unroll
    for (int k = 0; k < 8; k++) {
        buf[k][0] = m0[k*ST];
        buf[k][1] = xv ? m1[k*ST] : 0u;
        buf[k][2] = yv ? m2[k*ST] : 0u;
        buf[k][3] = (xv && yv) ? m3[k*ST] : 0u;
    }
    const unsigned *p0 = m0 + 8*ST, *p1p = m1 + 8*ST, *p2p = m2 + 8*ST, *p3p = m3 + 8*ST;
    unsigned int* op = g_M4 + w;
    float p1 = 0, q1 = 0, p2 = 0, q2 = 0;
#pragma unroll 1
    for (int t0 = 0; t0 < 296; t0 += 8) {
#pragma unroll
        for (int k = 0; k < 8; k++) {
            int cnt = ((buf[k][0] >> lane) & 1) + ((buf[k][1] >> lane) & 1)
                    + ((buf[k][2] >> lane) & 1) + ((buf[k][3] >> lane) & 1);
            buf[k][0] = *p0; p0 += ST;
            buf[k][1] = xv ? *p1p : 0u; p1p += ST;
            buf[k][2] = yv ? *p2p : 0u; p2p += ST;
            buf[k][3] = (xv && yv) ? *p3p : 0u; p3p += ST;
            float s = srm_step(p1, q1, p2, q2, 11.0f * (float)cnt);
            unsigned bal = __ballot_sync(0xffffffffu, s > 0.5f);
            if (!lane) *op = bal;
            op += NB*162;
        }
    }
#pragma unroll
    for (int k = 0; k < 4; k++) {
        int cnt = ((buf[k][0] >> lane) & 1) + ((buf[k][1] >> lane) & 1)
                + ((buf[k][2] >> lane) & 1) + ((buf[k][3] >> lane) & 1);
        float s = srm_step(p1, q1, p2, q2, 11.0f * (float)cnt);
        unsigned bal = __ballot_sync(0xffffffffu, s > 0.5f);
        if (!lane) *op = bal;
        op += NB*162;
    }
}

// ---------------- conv3 acc: warp per (t,b,x-PAIR), padded slot weights ----------------
__global__ void __launch_bounds__(256) conv3_acc() {
    int gw = blockIdx.x * 8 + (threadIdx.x >> 5);
    int lane = threadIdx.x & 31;
    if (gw >= TT*NB*45) return;                          // 9 rows x 5 pairs
    int pr = gw % 45, tb = gw / 45;
    int y = pr / 5, x0 = (pr % 5) * 2;
    bool x1v = (x0 + 1) < 9;
    const unsigned* mm = g_M4 + (size_t)tb*162;
    const float4* wl = g_Wt3x + lane;
    float a00 = 0.f, a01 = 0.f, a02 = 0.f;
    float a10 = 0.f, a11 = 0.f, a12 = 0.f;
#pragma unroll
    for (int ky = 0; ky < 3; ky++) {
        int yy = y + ky - 1;
        if (yy < 0 || yy >= 9) continue;
        const unsigned* row = mm + yy*18;
#pragma unroll
        for (int xi = 0; xi < 4; xi++) {                 // input cols x0-1 .. x0+2
            int xx = x0 - 1 + xi;
            unsigned mlo = 0u, mhi = 0u;
            if (xx >= 0 && xx < 9 && (xi < 3 || x1v)) {
                mlo = row[xx*2];
                mhi = row[xx*2 + 1];
            }
            while (mlo) {
                int c = __ffs(mlo) - 1; mlo &= mlo - 1;
                const float4* wb = wl + c*480 + (ky*5 + xi)*32;
                float4 w1v = wb[0];                      // pixel1
                float4 w0v = wb[32];                     // pixel0
                a00 += w0v.x; a01 += w0v.y; a02 += w0v.z;
                a10 += w1v.x; a11 += w1v.y; a12 += w1v.z;
            }
            while (mhi) {
                int c = __ffs(mhi) - 1; mhi &= mhi - 1;
                const float4* wb = wl + c*480 + 15360 + (ky*5 + xi)*32;   // (c+32)*480
                float4 w1v = wb[0];
                float4 w0v = wb[32];
                a00 += w0v.x; a01 += w0v.y; a02 += w0v.z;
                a10 += w1v.x; a11 += w1v.y; a12 += w1v.z;
            }
        }
    }
    size_t base = ((size_t)tb*81 + y*9 + x0)*96;
    g_A3[base + lane]      = a00;
    g_A3[base + 32 + lane] = a01;
    g_A3[base + 64 + lane] = a02;
    if (x1v) {
        g_A3[base + 96 + lane]  = a10;
        g_A3[base + 128 + lane] = a11;
        g_A3[base + 160 + lane] = a12;
    }
}

// ---------------- pool3 + SRM fused: warp per (b,opix,wrd), PF=8, rolling ptrs ----------------
__global__ void __launch_bounds__(512) pool3_srm() {
    int w = blockIdx.x * 16 + (threadIdx.x >> 5);
    int lane = threadIdx.x & 31;
    if (w >= NB*75) return;
    int b = w / 75, r = w % 75, pix = r / 3, wrd = r % 3;
    int y = pix / 5, x = pix % 5;
    bool xv = (2*x + 1) < 9, yv = (2*y + 1) < 9;
    const int ST = 972;                                  // words per t-plane
    const unsigned* m0 = g_M5 + b*243 + (2*y*9 + 2*x)*3 + wrd;
    const unsigned* m1 = m0 + 3;
    const unsigned* m2 = m0 + 27;
    const unsigned* m3 = m0 + 30;
    unsigned buf[8][4];
#pragma unroll
    for (int k = 0; k < 8; k++) {
        buf[k][0] = m0[k*ST];
        buf[k][1] = xv ? m1[k*ST] : 0u;
        buf[k][2] = yv ? m2[k*ST] : 0u;
        buf[k][3] = (xv && yv) ? m3[k*ST] : 0u;
    }
    const unsigned *p0 = m0 + 8*ST, *p1p = m1 + 8*ST, *p2p = m2 + 8*ST, *p3p = m3 + 8*ST;
    unsigned int* op = g_M6 + w;
    float p1 = 0, q1 = 0, p2 = 0, q2 = 0;
#pragma unroll 1
    for (int t0 = 0; t0 < 296; t0 += 8) {
#pragma unroll
        for (int k = 0; k < 8; k++) {
            int cnt = ((buf[k][0] >> lane) & 1) + ((buf[k][1] >> lane) & 1)
                    + ((buf[k][2] >> lane) & 1) + ((buf[k][3] >> lane) & 1);
            buf[k][0] = *p0; p0 += ST;
            buf[k][1] = xv ? *p1p : 0u; p1p += ST;
            buf[k][2] = yv ? *p2p : 0u; p2p += ST;
            buf[k][3] = (xv && yv) ? *p3p : 0u; p3p += ST;
            float s = srm_step(p1, q1, p2, q2, 11.0f * (float)cnt);
            unsigned bal = __ballot_sync(0xffffffffu, s > 0.5f);
            if (!lane) *op = bal;
            op += NB*75;
        }
    }
#pragma unroll
    for (int k = 0; k < 4; k++) {
        int cnt = ((buf[k][0] >> lane) & 1) + ((buf[k][1] >> lane) & 1)
                + ((buf[k][2] >> lane) & 1) + ((buf[k][3] >> lane) & 1);
        float s = srm_step(p1, q1, p2, q2, 11.0f * (float)cnt);
        unsigned bal = __ballot_sync(0xffffffffu, s > 0.5f);
        if (!lane) *op = bal;
        op += NB*75;
    }
}

// ---------------- dense1 (2400->256): WARP per (t,b), float4 weight rows ----------------
__global__ void __launch_bounds__(256) dense1() {
    int w = blockIdx.x * 8 + (threadIdx.x >> 5);
    int lane = threadIdx.x & 31;
    if (w >= TT*NB) return;
    const unsigned* m = g_M6 + (size_t)w*75;
    float4 acc0 = make_float4(0.f, 0.f, 0.f, 0.f);
    float4 acc1 = make_float4(0.f, 0.f, 0.f, 0.f);
    int pw = 0;
    for (int pos = 0; pos < 25; pos++) {
#pragma unroll
        for (int wrd = 0; wrd < 3; wrd++) {
            unsigned mm = m[pw++];
            int cb = wrd*32;
            while (mm) {
                int c = cb + __ffs(mm) - 1; mm &= mm - 1;
                const float4* wr = (const float4*)(g_Wt4 + (size_t)(c*25 + pos)*256) + lane;
                float4 v0 = wr[0], v1 = wr[32];
                acc0.x += v0.x; acc0.y += v0.y; acc0.z += v0.z; acc0.w += v0.w;
                acc1.x += v1.x; acc1.y += v1.y; acc1.z += v1.z; acc1.w += v1.w;
            }
        }
    }
    float4* op = (float4*)(g_A7 + (size_t)w*256) + lane;
    op[0]  = acc0;
    op[32] = acc1;
}

// ---------------- dense2 (256->10): warp per (t,b), writes transposed ----------------
__global__ void __launch_bounds__(256) dense2() {
    int w = blockIdx.x * 8 + (threadIdx.x >> 5);
    int lane = threadIdx.x & 31;
    if (w >= TT*NB) return;
    int t = w / NB, b = w % NB;
    if (lane < 16) {
        const unsigned* m = g_M7 + (size_t)w*8;
        float acc = 0.f;
        for (int wd = 0; wd < 8; wd++) {
            unsigned mm = m[wd];
            int ib = wd*32;
            while (mm) { int i = ib + __ffs(mm) - 1; mm &= mm - 1; acc += g_Wt5[i*16 + lane]; }
        }
        g_A8T[(size_t)(b*16 + lane)*TT + t] = acc;
    }
}

// ---------------- final SRM -> output spikes (B,10,T) ----------------
__global__ void srm_out(float* __restrict__ out) {
    int tid = threadIdx.x;
    if (tid >= 40) return;
    int b = tid / 10, o = tid % 10;
    const float* ip = g_A8T + (size_t)(b*16 + o)*TT;
    const int PF = 8;
    float buf[PF];
#pragma unroll
    for (int k = 0; k < PF; k++) buf[k] = ip[k];
    float p1 = 0, q1 = 0, p2 = 0, q2 = 0;
    float* op = out + (size_t)(b*10 + o)*TT;
    for (int t0 = 0; t0 < TT; t0 += PF) {
#pragma unroll
        for (int k = 0; k < PF; k++) {
            int t = t0 + k;
            if (t >= TT) break;
            float x = buf[k];
            int tn = t + PF;
            buf[k] = (tn < TT) ? ip[tn] : 0.f;
            op[t] = srm_step(p1, q1, p2, q2, x);
        }
    }
}

extern "C" void kernel_launch(void* const* d_in, const int* in_sizes, int n_in,
                              void* d_out, int out_size) {
    const float* s_in = (const float*)d_in[0];
    const float* Wc1  = (const float*)d_in[1];
    const float* Wc2  = (const float*)d_in[2];
    const float* Wc3  = (const float*)d_in[3];
    const float* Wd4a = (const float*)d_in[4];
    const float* Wd4b = (const float*)d_in[5];
    float* out = (float*)d_out;

    // slots 0..2 so conv1_acc lands in the profiled 4th slot
    init_weights<<<90, 256>>>(Wc1, Wc2, Wc3, Wd4b);
    pack_input<<<(NB*2*34*10 + 15)/16, 512>>>(s_in);
    prep_wt4<<<dim3(75, 8), dim3(32, 8)>>>(Wd4a);

    conv1_acc<<<(TT*NB*306 + 7)/8, 256>>>();
    srm_scan_L1<<<(NB*1156 + 15)/16, 512>>>();
    pool1_srm<<<(NB*289 + 15)/16, 512>>>();

    conv2_acc<<<(TT*NB*153 + 7)/8, 256>>>();
    srm_scan_L2<<<(NB*289*2 + 15)/16, 512>>>();
    pool2_srm<<<(NB*162 + 15)/16, 512>>>();

    conv3_acc<<<(TT*NB*45 + 7)/8, 256>>>();
    srm_scan_L3<<<(NB*81*3 + 15)/16, 512>>>();
    pool3_srm<<<(NB*75 + 15)/16, 512>>>();

    dense1<<<(TT*NB + 7)/8, 256>>>();
    srm_scan_D1<<<2, 512>>>();

    dense2<<<(TT*NB + 7)/8, 256>>>();
    srm_out<<<1, 64>>>(out);
}